// round 15
// baseline (speedup 1.0000x reference)
#include <cuda_runtime.h>
#include <cuda_fp16.h>
#include <cuda_bf16.h>
#include <math.h>
#include <stdint.h>

#define Bb 2
#define Tt 2048
#define Ee 1024
#define Dd 64
#define BH 32
#define BT 4096  // B*T

static const size_t OUT_OFF = (size_t)Bb * Tt * Ee;  // floats of `out`, then weights

// ---------------- scratch (device globals; no allocation allowed) ----------------
__device__ float g_q[BT * Ee];
__device__ float g_k[BT * Ee];
__device__ float g_v[BT * Ee];
__device__ float g_attn[BT * Ee];

__device__ __nv_bfloat16 g_ahi[BT * Ee];           // activation split (reused)
__device__ __nv_bfloat16 g_alo[BT * Ee];
__device__ __nv_bfloat16 g_whi[Ee * Ee];           // weight split (reused)
__device__ __nv_bfloat16 g_wlo[Ee * Ee];
__device__ __nv_bfloat16 g_qrhi[BH * Tt * Dd];
__device__ __nv_bfloat16 g_qrlo[BH * Tt * Dd];
__device__ __nv_bfloat16 g_krhi[BH * Tt * Dd];
__device__ __nv_bfloat16 g_krlo[BH * Tt * Dd];
__device__ __nv_bfloat16 g_vthi[BH * Dd * Tt];     // [bh, d, t]
__device__ __nv_bfloat16 g_vtlo[BH * Dd * Tt];

// ================= low-level helpers (sm_80-class ISA only) =================
__device__ __forceinline__ uint32_t smem_u32(const void* p) {
    uint32_t a;
    asm("{ .reg .u64 t; cvta.to.shared.u64 t, %1; cvt.u32.u64 %0, t; }" : "=r"(a) : "l"(p));
    return a;
}
__device__ __forceinline__ void cpa16(uint32_t s, const void* g) {
    asm volatile("cp.async.ca.shared.global [%0], [%1], 16;" :: "r"(s), "l"(g));
}
#define CP_COMMIT() asm volatile("cp.async.commit_group;" ::: "memory")
#define CP_WAIT0()  asm volatile("cp.async.wait_group 0;" ::: "memory")
#define CP_WAIT1()  asm volatile("cp.async.wait_group 1;" ::: "memory")

__device__ __forceinline__ void ldsm4(uint32_t* r, uint32_t a) {
    asm volatile("ldmatrix.sync.aligned.m8n8.x4.shared.b16 {%0,%1,%2,%3}, [%4];"
                 : "=r"(r[0]), "=r"(r[1]), "=r"(r[2]), "=r"(r[3]) : "r"(a));
}
__device__ __forceinline__ void mma_bf16(float* d, const uint32_t* a, const uint32_t* b) {
    asm volatile("mma.sync.aligned.m16n8k16.row.col.f32.bf16.bf16.f32 "
                 "{%0,%1,%2,%3}, {%4,%5,%6,%7}, {%8,%9}, {%0,%1,%2,%3};"
                 : "+f"(d[0]), "+f"(d[1]), "+f"(d[2]), "+f"(d[3])
                 : "r"(a[0]), "r"(a[1]), "r"(a[2]), "r"(a[3]), "r"(b[0]), "r"(b[1]));
}
__device__ __forceinline__ uint32_t sw128(uint32_t off) { return off ^ ((off >> 3) & 0x70); }

// ================= bf16x3 NT GEMM on mma.sync (projections / out-proj) =================
template <int BN>
__global__ void __launch_bounds__(256)
mma_gemm(const __nv_bfloat16* __restrict__ Ahi, const __nv_bfloat16* __restrict__ Alo,
         const __nv_bfloat16* __restrict__ Bhi, const __nv_bfloat16* __restrict__ Blo,
         const float* __restrict__ bias, float* __restrict__ C,
         int M, int N, int K, int lda, int ldb, int ldc)
{
    constexpr int WN = BN / 2;
    constexpr int NT = WN / 8;
    constexpr int A_HI = 0;
    constexpr int A_LO = 16384;
    constexpr int B_HI = 32768;
    constexpr int B_LO = 32768 + BN * 128;
    constexpr int STAGE = 32768 + BN * 256;

    extern __shared__ char smem[];
    uint32_t smemU = smem_u32(smem);

    int tid = threadIdx.x;
    int wid = tid >> 5, lid = tid & 31;
    int row0 = blockIdx.y * 128;
    int col0 = blockIdx.x * BN;
    int wm0 = (wid & 3) * 32;
    int wn0 = (wid >> 2) * WN;

    float acc[2][NT][4];
#pragma unroll
    for (int mt = 0; mt < 2; mt++)
#pragma unroll
        for (int nt = 0; nt < NT; nt++)
#pragma unroll
            for (int j = 0; j < 4; j++) acc[mt][nt][j] = 0.0f;

    int NC = K >> 6;

    auto load_chunk = [&](int ch, int buf) {
        uint32_t s0 = smemU + buf * STAGE;
        int k0 = ch << 6;
#pragma unroll
        for (int i = 0; i < 4; i++) {
            int u = tid + i * 256;
            int r = u >> 3, ce = (u & 7) << 3;
            uint32_t sw = sw128((uint32_t)u << 4);
            size_t g = (size_t)(row0 + r) * lda + k0 + ce;
            cpa16(s0 + A_HI + sw, Ahi + g);
            cpa16(s0 + A_LO + sw, Alo + g);
        }
#pragma unroll
        for (int i = 0; i < BN / 32; i++) {
            int u = tid + i * 256;
            int r = u >> 3, ce = (u & 7) << 3;
            uint32_t sw = sw128((uint32_t)u << 4);
            size_t g = (size_t)(col0 + r) * ldb + k0 + ce;
            cpa16(s0 + B_HI + sw, Bhi + g);
            cpa16(s0 + B_LO + sw, Blo + g);
        }
    };

    int aR = lid & 15;
    int aK = (lid >> 4) << 4;
    int bR = (lid & 7) + ((lid >> 4) << 3);
    int bK = ((lid >> 3) & 1) << 4;

    load_chunk(0, 0);
    CP_COMMIT();

    for (int ch = 0; ch < NC; ch++) {
        if (ch + 1 < NC) {
            load_chunk(ch + 1, (ch + 1) & 1);
            CP_COMMIT();
            CP_WAIT1();
        } else {
            CP_WAIT0();
        }
        __syncthreads();

        uint32_t sbase = smemU + (ch & 1) * STAGE;
#pragma unroll
        for (int ks = 0; ks < 4; ks++) {
            uint32_t ah[2][4], al[2][4];
#pragma unroll
            for (int mt = 0; mt < 2; mt++) {
                uint32_t off = (uint32_t)(wm0 + mt * 16 + aR) * 128 + (ks << 5) + aK;
                uint32_t sw = sw128(off);
                ldsm4(ah[mt], sbase + A_HI + sw);
                ldsm4(al[mt], sbase + A_LO + sw);
            }
#pragma unroll
            for (int np = 0; np < NT / 2; np++) {
                uint32_t off = (uint32_t)(wn0 + np * 16 + bR) * 128 + (ks << 5) + bK;
                uint32_t sw = sw128(off);
                uint32_t bh[4], bl[4];
                ldsm4(bh, sbase + B_HI + sw);
                ldsm4(bl, sbase + B_LO + sw);
#pragma unroll
                for (int mt = 0; mt < 2; mt++) {
                    mma_bf16(acc[mt][2 * np],     ah[mt], bh);
                    mma_bf16(acc[mt][2 * np],     ah[mt], bl);
                    mma_bf16(acc[mt][2 * np],     al[mt], bh);
                    mma_bf16(acc[mt][2 * np + 1], ah[mt], bh + 2);
                    mma_bf16(acc[mt][2 * np + 1], ah[mt], bl + 2);
                    mma_bf16(acc[mt][2 * np + 1], al[mt], bh + 2);
                }
            }
        }
        __syncthreads();
    }

    int g = lid >> 2, tig = lid & 3;
#pragma unroll
    for (int mt = 0; mt < 2; mt++) {
#pragma unroll
        for (int nt = 0; nt < NT; nt++) {
            int r = row0 + wm0 + mt * 16 + g;
            int c = col0 + wn0 + nt * 8 + 2 * tig;
            float bx = 0.0f, by = 0.0f;
            if (bias) { bx = bias[c]; by = bias[c + 1]; }
            float2 v0 = make_float2(acc[mt][nt][0] + bx, acc[mt][nt][1] + by);
            float2 v1 = make_float2(acc[mt][nt][2] + bx, acc[mt][nt][3] + by);
            *reinterpret_cast<float2*>(&C[(size_t)r * ldc + c]) = v0;
            *reinterpret_cast<float2*>(&C[(size_t)(r + 8) * ldc + c]) = v1;
        }
    }
}

// ================= fused attention: QK^T + softmax + weights-out + PV =================
// Grid: (16 q-stripes, 32 bh). One CTA = 128 q-rows. Two passes over 16 K-tiles.
__global__ void __launch_bounds__(256, 1)
fused_attn(const __nv_bfloat16* __restrict__ QHg, const __nv_bfloat16* __restrict__ QLg,
           const __nv_bfloat16* __restrict__ KHg, const __nv_bfloat16* __restrict__ KLg,
           const __nv_bfloat16* __restrict__ VHg, const __nv_bfloat16* __restrict__ VLg,
           float* __restrict__ wout, float* __restrict__ attn)
{
    // smem byte offsets (total 232448 = sm_103 max dynamic)
    constexpr int Q_HI = 0, Q_LO = 16384;
    constexpr int K_B  = 32768;    // + buf*32768 (hi), +16384 (lo)
    constexpr int V_B  = 98304;    // + buf*32768 (hi), +16384 (lo); each: [2 chunks of 8192][64r][128B]
    constexpr int P_HI = 163840, P_LO = 196608;   // [2 chunks of 16384][128r][128B]
    constexpr int R_M = 229376, R_L = 229888, R_T = 230400, R_S = 231424;

    extern __shared__ char smem[];
    uint32_t sU = smem_u32(smem);
    float* rowm = (float*)(smem + R_M);
    float* rowl = (float*)(smem + R_L);
    float* tmax = (float*)(smem + R_T);   // [2][128]; [0] reused as corr
    float* tsum = (float*)(smem + R_S);   // [2][128]

    int tid = threadIdx.x, wid = tid >> 5, lid = tid & 31;
    int wm0 = (wid & 3) * 32;
    int wnS = (wid >> 2) * 64;     // score-tile n offset
    int wnP = (wid >> 2) * 32;     // PV n offset
    int wn = wid >> 2;
    int g = lid >> 2, q4 = lid & 3;
    int bh = blockIdx.y, t0 = blockIdx.x * 128;
    int b = bh >> 4, h = bh & 15;

    const __nv_bfloat16* qh = QHg + ((size_t)bh * 2048 + t0) * 64;
    const __nv_bfloat16* ql = QLg + ((size_t)bh * 2048 + t0) * 64;
    const __nv_bfloat16* kh = KHg + (size_t)bh * 2048 * 64;
    const __nv_bfloat16* kl = KLg + (size_t)bh * 2048 * 64;
    const __nv_bfloat16* vh = VHg + (size_t)bh * 64 * 2048;
    const __nv_bfloat16* vl = VLg + (size_t)bh * 64 * 2048;

    int aR = lid & 15, aK = (lid >> 4) << 4;
    int bR = (lid & 7) + ((lid >> 4) << 3), bK = ((lid >> 3) & 1) << 4;

    // ---- load Q (persistent) ----
#pragma unroll
    for (int i = 0; i < 4; i++) {
        int u = tid + i * 256;
        int r = u >> 3, cu = u & 7;
        uint32_t sw = sw128((uint32_t)u << 4);
        cpa16(sU + Q_HI + sw, qh + (size_t)r * 64 + cu * 8);
        cpa16(sU + Q_LO + sw, ql + (size_t)r * 64 + cu * 8);
    }

    auto loadK = [&](int j, int buf) {
        uint32_t kb = sU + K_B + buf * 32768;
#pragma unroll
        for (int i = 0; i < 4; i++) {
            int u = tid + i * 256;
            int r = u >> 3, cu = u & 7;
            uint32_t sw = sw128((uint32_t)u << 4);
            size_t gg = (size_t)(j * 128 + r) * 64 + cu * 8;
            cpa16(kb + sw, kh + gg);
            cpa16(kb + 16384 + sw, kl + gg);
        }
    };
    auto loadV = [&](int j, int buf) {
        uint32_t vb = sU + V_B + buf * 32768;
#pragma unroll
        for (int i = 0; i < 4; i++) {
            int u = tid + i * 256;
            int ck = u >> 9, w = u & 511;
            int r = w >> 3, cu = w & 7;
            uint32_t sw = sw128((uint32_t)w << 4) + ck * 8192;   // chunk stride = 64r*128B
            size_t gg = (size_t)r * 2048 + j * 128 + ck * 64 + cu * 8;
            cpa16(vb + sw, vh + gg);
            cpa16(vb + 16384 + sw, vl + gg);
        }
    };

    if (tid < 128) { rowm[tid] = -INFINITY; rowl[tid] = 0.0f; }

    float sacc[2][8][4];
    auto computeS = [&](int buf) {
#pragma unroll
        for (int mt = 0; mt < 2; mt++)
#pragma unroll
            for (int nt = 0; nt < 8; nt++)
#pragma unroll
                for (int j2 = 0; j2 < 4; j2++) sacc[mt][nt][j2] = 0.0f;
        uint32_t kb = sU + K_B + buf * 32768;
#pragma unroll
        for (int ks = 0; ks < 4; ks++) {
            uint32_t ah[2][4], al[2][4];
#pragma unroll
            for (int mt = 0; mt < 2; mt++) {
                uint32_t off = (uint32_t)(wm0 + mt * 16 + aR) * 128 + (ks << 5) + aK;
                uint32_t sw = sw128(off);
                ldsm4(ah[mt], sU + Q_HI + sw);
                ldsm4(al[mt], sU + Q_LO + sw);
            }
#pragma unroll
            for (int np = 0; np < 4; np++) {
                uint32_t off = (uint32_t)(wnS + np * 16 + bR) * 128 + (ks << 5) + bK;
                uint32_t sw = sw128(off);
                uint32_t bh4[4], bl4[4];
                ldsm4(bh4, kb + sw);
                ldsm4(bl4, kb + 16384 + sw);
#pragma unroll
                for (int mt = 0; mt < 2; mt++) {
                    mma_bf16(sacc[mt][2 * np],     ah[mt], bh4);
                    mma_bf16(sacc[mt][2 * np],     ah[mt], bl4);
                    mma_bf16(sacc[mt][2 * np],     al[mt], bh4);
                    mma_bf16(sacc[mt][2 * np + 1], ah[mt], bh4 + 2);
                    mma_bf16(sacc[mt][2 * np + 1], ah[mt], bl4 + 2);
                    mma_bf16(sacc[mt][2 * np + 1], al[mt], bh4 + 2);
                }
            }
        }
    };

    // ================ pass A: online softmax stats ================
    loadK(0, 0);
    CP_COMMIT();
    for (int j = 0; j < 16; j++) {
        if (j < 15) { loadK(j + 1, (j + 1) & 1); CP_COMMIT(); CP_WAIT1(); }
        else        { CP_WAIT0(); }
        __syncthreads();
        computeS(j & 1);

        // tile row maxes
#pragma unroll
        for (int k = 0; k < 4; k++) {
            int mt = k >> 1, hf = k & 1;
            float mv = -INFINITY;
#pragma unroll
            for (int nt = 0; nt < 8; nt++)
                mv = fmaxf(mv, fmaxf(sacc[mt][nt][hf * 2], sacc[mt][nt][hf * 2 + 1]));
            mv = fmaxf(mv, __shfl_xor_sync(0xffffffffu, mv, 1));
            mv = fmaxf(mv, __shfl_xor_sync(0xffffffffu, mv, 2));
            if (q4 == 0) tmax[wn * 128 + wm0 + mt * 16 + g + hf * 8] = mv;
        }
        __syncthreads();
        if (tid < 128) {
            float mo = rowm[tid];
            float mn = fmaxf(mo, fmaxf(tmax[tid], tmax[128 + tid]));
            rowm[tid] = mn;
            tmax[tid] = expf(mo - mn);     // corr factor (0 when mo = -inf)
        }
        __syncthreads();
        // tile row sums of exp(s - m_new)
#pragma unroll
        for (int k = 0; k < 4; k++) {
            int mt = k >> 1, hf = k & 1;
            int r = wm0 + mt * 16 + g + hf * 8;
            float mn = rowm[r];
            float s = 0.0f;
#pragma unroll
            for (int nt = 0; nt < 8; nt++)
                s += expf(sacc[mt][nt][hf * 2] - mn) + expf(sacc[mt][nt][hf * 2 + 1] - mn);
            s += __shfl_xor_sync(0xffffffffu, s, 1);
            s += __shfl_xor_sync(0xffffffffu, s, 2);
            if (q4 == 0) tsum[wn * 128 + r] = s;
        }
        __syncthreads();
        if (tid < 128)
            rowl[tid] = rowl[tid] * tmax[tid] + tsum[tid] + tsum[128 + tid];
    }

    if (tid < 128) rowl[tid] = 1.0f / rowl[tid];   // same thread that wrote it

    // ================ pass B: recompute S, write weights, PV ================
    float pv[2][4][4];
#pragma unroll
    for (int mt = 0; mt < 2; mt++)
#pragma unroll
        for (int nt = 0; nt < 4; nt++)
#pragma unroll
            for (int j2 = 0; j2 < 4; j2++) pv[mt][nt][j2] = 0.0f;

    loadK(0, 0); loadV(0, 0);
    CP_COMMIT();
    float* wbase = wout + ((size_t)((h * 2 + b) * 2048 + t0)) * 2048;

    for (int j = 0; j < 16; j++) {
        if (j < 15) { loadK(j + 1, (j + 1) & 1); loadV(j + 1, (j + 1) & 1); CP_COMMIT(); CP_WAIT1(); }
        else        { CP_WAIT0(); }
        __syncthreads();
        computeS(j & 1);

        // probs: quantize, write d_out weights, fill P smem (bf16 hi/lo, exact)
#pragma unroll
        for (int mt = 0; mt < 2; mt++) {
#pragma unroll
            for (int hf = 0; hf < 2; hf++) {
                int r = wm0 + mt * 16 + g + hf * 8;
                float mn = rowm[r], inv = rowl[r];
                float* wrow = wbase + (size_t)r * 2048 + j * 128;
#pragma unroll
                for (int nt = 0; nt < 8; nt++) {
                    int c = wnS + nt * 8 + 2 * q4;
                    float p0 = expf(sacc[mt][nt][hf * 2]     - mn) * inv;
                    float p1 = expf(sacc[mt][nt][hf * 2 + 1] - mn) * inv;
                    __half h0 = __float2half(p0), h1 = __float2half(p1);
                    float f0 = __half2float(h0), f1 = __half2float(h1);
                    *reinterpret_cast<float2*>(wrow + c) = make_float2(f0, f1);
                    __nv_bfloat16 b0 = __float2bfloat16(f0), b1 = __float2bfloat16(f1);
                    __nv_bfloat16 l0 = __float2bfloat16(f0 - __bfloat162float(b0));
                    __nv_bfloat16 l1 = __float2bfloat16(f1 - __bfloat162float(b1));
                    __nv_bfloat162 hvv = __halves2bfloat162(b0, b1);
                    __nv_bfloat162 lvv = __halves2bfloat162(l0, l1);
                    int ck = c >> 6, c64 = c & 63;
                    uint32_t off = (uint32_t)r * 128 + c64 * 2;
                    uint32_t sw = sw128(off) + ck * 16384;
                    *reinterpret_cast<uint32_t*>(smem + P_HI + sw) = reinterpret_cast<uint32_t&>(hvv);
                    *reinterpret_cast<uint32_t*>(smem + P_LO + sw) = reinterpret_cast<uint32_t&>(lvv);
                }
            }
        }
        __syncthreads();

        // PV: attn[128, 64] += P[128, 128] @ V_j^T  (3-term bf16x3)
        uint32_t vb = sU + V_B + (j & 1) * 32768;
#pragma unroll
        for (int ck = 0; ck < 2; ck++) {
#pragma unroll
            for (int ks = 0; ks < 4; ks++) {
                uint32_t ph4[2][4], pl4[2][4];
#pragma unroll
                for (int mt = 0; mt < 2; mt++) {
                    uint32_t off = (uint32_t)(wm0 + mt * 16 + aR) * 128 + (ks << 5) + aK;
                    uint32_t sw = sw128(off) + ck * 16384;
                    ldsm4(ph4[mt], sU + P_HI + sw);
                    ldsm4(pl4[mt], sU + P_LO + sw);
                }
#pragma unroll
                for (int np = 0; np < 2; np++) {
                    uint32_t off = (uint32_t)(wnP + np * 16 + bR) * 128 + (ks << 5) + bK;
                    uint32_t sw = sw128(off) + ck * 8192;   // V chunk stride = 8192
                    uint32_t vh4[4], vl4[4];
                    ldsm4(vh4, vb + sw);
                    ldsm4(vl4, vb + 16384 + sw);
#pragma unroll
                    for (int mt = 0; mt < 2; mt++) {
                        mma_bf16(pv[mt][2 * np],     ph4[mt], vh4);
                        mma_bf16(pv[mt][2 * np],     ph4[mt], vl4);
                        mma_bf16(pv[mt][2 * np],     pl4[mt], vh4);
                        mma_bf16(pv[mt][2 * np + 1], ph4[mt], vh4 + 2);
                        mma_bf16(pv[mt][2 * np + 1], ph4[mt], vl4 + 2);
                        mma_bf16(pv[mt][2 * np + 1], pl4[mt], vh4 + 2);
                    }
                }
            }
        }
        __syncthreads();
    }

    // ---- attn epilogue: [b, t, h*64 + d] ----
    float* ab = attn + (size_t)b * 2048 * 1024 + (size_t)t0 * 1024 + h * 64;
#pragma unroll
    for (int mt = 0; mt < 2; mt++) {
#pragma unroll
        for (int nt = 0; nt < 4; nt++) {
            int r = wm0 + mt * 16 + g;
            int c = wnP + nt * 8 + 2 * q4;
            *reinterpret_cast<float2*>(&ab[(size_t)r * 1024 + c]) =
                make_float2(pv[mt][nt][0], pv[mt][nt][1]);
            *reinterpret_cast<float2*>(&ab[(size_t)(r + 8) * 1024 + c]) =
                make_float2(pv[mt][nt][2], pv[mt][nt][3]);
        }
    }
}

// ================= fp32 -> bf16 hi/lo split (vectorized) =================
__global__ void __launch_bounds__(256)
split_f32(const float4* __restrict__ x, uint2* __restrict__ hi,
          uint2* __restrict__ lo, int n4)
{
    int i = blockIdx.x * blockDim.x + threadIdx.x;
    if (i >= n4) return;
    float4 v = x[i];
    __nv_bfloat16 h0 = __float2bfloat16(v.x), h1 = __float2bfloat16(v.y);
    __nv_bfloat16 h2 = __float2bfloat16(v.z), h3 = __float2bfloat16(v.w);
    __nv_bfloat16 l0 = __float2bfloat16(v.x - __bfloat162float(h0));
    __nv_bfloat16 l1 = __float2bfloat16(v.y - __bfloat162float(h1));
    __nv_bfloat16 l2 = __float2bfloat16(v.z - __bfloat162float(h2));
    __nv_bfloat16 l3 = __float2bfloat16(v.w - __bfloat162float(h3));
    __nv_bfloat162 ha = __halves2bfloat162(h0, h1), hb = __halves2bfloat162(h2, h3);
    __nv_bfloat162 la = __halves2bfloat162(l0, l1), lb = __halves2bfloat162(l2, l3);
    hi[i] = make_uint2(reinterpret_cast<uint32_t&>(ha), reinterpret_cast<uint32_t&>(hb));
    lo[i] = make_uint2(reinterpret_cast<uint32_t&>(la), reinterpret_cast<uint32_t&>(lb));
}

// ================= prune via radix select + head split + xPos, bf16 hi/lo out =================
__global__ void __launch_bounds__(1024)
prune_radix(const float* __restrict__ Xv, const float* __restrict__ Xq, const float* __restrict__ Xk,
            __nv_bfloat16* __restrict__ VH, __nv_bfloat16* __restrict__ VL,
            __nv_bfloat16* __restrict__ QH, __nv_bfloat16* __restrict__ QL,
            __nv_bfloat16* __restrict__ KH, __nv_bfloat16* __restrict__ KL)
{
    int mode = blockIdx.y;
    const float* X = (mode == 0) ? Xv : (mode == 1) ? Xq : Xk;
    __nv_bfloat16* OH = (mode == 0) ? VH : (mode == 1) ? QH : KH;
    __nv_bfloat16* OL = (mode == 0) ? VL : (mode == 1) ? QL : KL;

    int row = blockIdx.x;
    int b = row >> 11;
    int t = row & 2047;
    int e = threadIdx.x;

    __shared__ uint32_t hist[256];
    __shared__ uint32_t s_bin;

    float x = X[(size_t)row * 1024 + e];
    uint32_t bits = __float_as_uint(x);
    uint32_t u = bits ^ ((uint32_t)((int)bits >> 31) | 0x80000000u);

    uint32_t prefix = 0;
    bool active = true;
    uint32_t tgt = 512;
#pragma unroll
    for (int shift = 24; shift >= 0; shift -= 8) {
        if (e < 256) hist[e] = 0;
        __syncthreads();
        if (active) atomicAdd(&hist[(u >> shift) & 255], 1);
        __syncthreads();
        if (e < 32) {
            uint32_t cnt[8], lsum = 0;
#pragma unroll
            for (int j = 0; j < 8; j++) { cnt[j] = hist[e * 8 + j]; lsum += cnt[j]; }
            uint32_t inc = lsum;
#pragma unroll
            for (int o = 1; o < 32; o <<= 1) {
                uint32_t vv = __shfl_up_sync(0xffffffffu, inc, o);
                if (e >= o) inc += vv;
            }
            uint32_t exc = inc - lsum;
            bool has = (exc <= tgt) && (tgt < inc);
            uint32_t binv = 0, ntgt = 0;
            if (has) {
                uint32_t c = exc;
                bool done = false;
#pragma unroll
                for (int j = 0; j < 8; j++) {
                    uint32_t nc = c + cnt[j];
                    if (!done && tgt < nc) { binv = e * 8 + j; ntgt = tgt - c; done = true; }
                    c = nc;
                }
            }
            uint32_t bal = __ballot_sync(0xffffffffu, has);
            int src = __ffs(bal) - 1;
            binv = __shfl_sync(0xffffffffu, binv, src);
            tgt  = __shfl_sync(0xffffffffu, ntgt, src);
            if (e == 0) s_bin = binv;
        }
        __syncthreads();
        uint32_t bin = s_bin;
        prefix |= bin << shift;
        active = active && (((u >> shift) & 255) == bin);
        __syncthreads();
    }

    uint32_t tb = (prefix & 0x80000000u) ? (prefix ^ 0x80000000u) : ~prefix;
    float thr = __uint_as_float(tb);
    float m = (x >= thr) ? x : 0.0f;

    int h = e >> 6, d = e & 63;
    if (mode == 0) {
        size_t idx = ((size_t)(b * 16 + h) * 64 + d) * 2048 + t;
        __nv_bfloat16 mh = __float2bfloat16(m);
        OH[idx] = mh;
        OL[idx] = __float2bfloat16(m - __bfloat162float(mh));
        return;
    }
    if (mode == 1) m *= 0.125f;

    int i = d >> 1;
    float base = (2.0f * (float)i + 25.6f) / 89.6f;
    float p = ((float)t - 1024.0f) / 512.0f;
    if (mode == 2) p = -p;
    float scl = powf(base, p);
    float freq = powf(10000.0f, -(float)i / 32.0f);
    float ang = (float)t * freq;
    float sn = sinf(ang) * scl;
    float cs = cosf(ang) * scl;
    float partner = __shfl_xor_sync(0xffffffffu, m, 1);
    float o = (d & 1) ? (m * cs + partner * sn) : (m * cs - partner * sn);
    size_t idx = ((size_t)(b * 16 + h) * 2048 + t) * 64 + d;
    __nv_bfloat16 oh = __float2bfloat16(o);
    OH[idx] = oh;
    OL[idx] = __float2bfloat16(o - __bfloat162float(oh));
}

// ================= host =================
extern "C" void kernel_launch(void* const* d_in, const int* in_sizes, int n_in,
                              void* d_out, int out_size)
{
    const float* query = (const float*)d_in[0];
    const float* key   = (const float*)d_in[1];
    const float* value = (const float*)d_in[2];
    const float* Wq = (const float*)d_in[3];
    const float* bq = (const float*)d_in[4];
    const float* Wk = (const float*)d_in[5];
    const float* bk = (const float*)d_in[6];
    const float* Wv = (const float*)d_in[7];
    const float* bv = (const float*)d_in[8];
    const float* Wo = (const float*)d_in[9];
    const float* bo = (const float*)d_in[10];
    float* out = (float*)d_out;

    float *qp, *kp, *vp, *at;
    __nv_bfloat16 *ahi, *alo, *whi, *wlo, *qrh, *qrl, *krh, *krl, *vth, *vtl;
    cudaGetSymbolAddress((void**)&qp, g_q);
    cudaGetSymbolAddress((void**)&kp, g_k);
    cudaGetSymbolAddress((void**)&vp, g_v);
    cudaGetSymbolAddress((void**)&at, g_attn);
    cudaGetSymbolAddress((void**)&ahi, g_ahi);
    cudaGetSymbolAddress((void**)&alo, g_alo);
    cudaGetSymbolAddress((void**)&whi, g_whi);
    cudaGetSymbolAddress((void**)&wlo, g_wlo);
    cudaGetSymbolAddress((void**)&qrh, g_qrhi);
    cudaGetSymbolAddress((void**)&qrl, g_qrlo);
    cudaGetSymbolAddress((void**)&krh, g_krhi);
    cudaGetSymbolAddress((void**)&krl, g_krlo);
    cudaGetSymbolAddress((void**)&vth, g_vthi);
    cudaGetSymbolAddress((void**)&vtl, g_vtlo);

    const int SM128 = 2 * (32768 + 128 * 256);   // 128 KB
    const int SMFA  = 232448;                    // fused attention (max)
    cudaFuncSetAttribute(mma_gemm<128>, cudaFuncAttributeMaxDynamicSharedMemorySize, SM128);
    cudaFuncSetAttribute(fused_attn,    cudaFuncAttributeMaxDynamicSharedMemorySize, SMFA);

    const int NE = BT * Ee;
    const int NW = Ee * Ee;

    // --- projections (bf16x3 HMMA, fp32 out) ---
    struct { const float *x, *W, *b; float* C; } proj[3] = {
        {query, Wq, bq, qp}, {key, Wk, bk, kp}, {value, Wv, bv, vp}
    };
    for (int p = 0; p < 3; p++) {
        split_f32<<<(NE / 4 + 255) / 256, 256>>>((const float4*)proj[p].x, (uint2*)ahi, (uint2*)alo, NE / 4);
        split_f32<<<(NW / 4 + 255) / 256, 256>>>((const float4*)proj[p].W, (uint2*)whi, (uint2*)wlo, NW / 4);
        dim3 grid(Ee / 128, BT / 128, 1);
        mma_gemm<128><<<grid, 256, SM128>>>(
            ahi, alo, whi, wlo, proj[p].b, proj[p].C, BT, Ee, Ee, Ee, Ee, Ee);
    }

    // --- prune (radix select) + split heads + xPos ---
    {
        dim3 grid(BT, 3);
        prune_radix<<<grid, 1024>>>(vp, qp, kp, vth, vtl, qrh, qrl, krh, krl);
    }

    // --- fused attention: scores + softmax + weights-out + PV ---
    {
        dim3 grid(Tt / 128, BH);
        fused_attn<<<grid, 256, SMFA>>>(qrh, qrl, krh, krl, vth, vtl, out + OUT_OFF, at);
    }

    // --- output projection ---
    {
        split_f32<<<(NE / 4 + 255) / 256, 256>>>((const float4*)at, (uint2*)ahi, (uint2*)alo, NE / 4);
        split_f32<<<(NW / 4 + 255) / 256, 256>>>((const float4*)Wo, (uint2*)whi, (uint2*)wlo, NW / 4);
        dim3 grid(Ee / 128, BT / 128, 1);
        mma_gemm<128><<<grid, 256, SM128>>>(
            ahi, alo, whi, wlo, bo, out, BT, Ee, Ee, Ee, Ee, Ee);
    }
}